// round 7
// baseline (speedup 1.0000x reference)
#include <cuda_runtime.h>

// Mandelbrot boundary-proximity loss. R7: state-carrying 3-stage pipeline.
//   phase 1 : all N, K1=6 iters, cardioid/bulb filter, 4 pts/thread;
//             survivors stored as float4{cr,ci,zr,zi} (z after iter 6).
//   phase 2a: survivors continue iters 7..38 (32), chunk-8 + warp vote;
//             alive points re-stored with z after iter 38.
//   phase 2b: continue iters 39..102 (64; overrun clamped: cnt>99 -> dist=70,
//             exact since reference caps at 100). Fused last-block finalize.
// Continuation from stored state is the same float sequence as replay =>
// classification identical to the validated R1/R6 arithmetic. Cycle check
// omitted (value-neutral: in_cycle => iters=100 == exhaustion).
// Reduction: exact integer ULL sum => deterministic.

#define NMAX 8388608
#define K1 6
#define P1_THREADS 256
#define P1_PTS 4
#define P2A_BLOCKS 4096
#define P2B_BLOCKS 2048
#define P2_THREADS 256

__device__ unsigned long long g_sum;   // zero-init at load
__device__ unsigned int g_ns1;         // survivors after phase 1
__device__ unsigned int g_ns2;         // survivors after phase 2a
__device__ unsigned int g_done;
__device__ float4 g_st1[NMAX];         // {cr, ci, zr, zi} at iter 6
__device__ float4 g_st2[NMAX];         // {cr, ci, zr, zi} at iter 38

// ---------------------------------------------------------------- phase 1
__global__ void __launch_bounds__(P1_THREADS) phase1_kernel(
    const float* __restrict__ c_real,
    const float* __restrict__ c_imag,
    int n)
{
    const int tid  = blockIdx.x * P1_THREADS + threadIdx.x;
    const int base = tid * P1_PTS;
    const int lane = threadIdx.x & 31;
    const int wid  = threadIdx.x >> 5;

    float cr[P1_PTS], ci[P1_PTS];
    bool valid[P1_PTS];

    if (base + P1_PTS - 1 < n) {
        const float4 r4 = *reinterpret_cast<const float4*>(c_real + base);
        const float4 i4 = *reinterpret_cast<const float4*>(c_imag + base);
        cr[0] = r4.x; cr[1] = r4.y; cr[2] = r4.z; cr[3] = r4.w;
        ci[0] = i4.x; ci[1] = i4.y; ci[2] = i4.z; ci[3] = i4.w;
        #pragma unroll
        for (int p = 0; p < P1_PTS; ++p) valid[p] = true;
    } else {
        #pragma unroll
        for (int p = 0; p < P1_PTS; ++p) {
            valid[p] = (base + p) < n;
            cr[p] = valid[p] ? c_real[base + p] : 10.0f;  // dummy escapes fast
            ci[p] = valid[p] ? c_imag[base + p] : 0.0f;
        }
    }

    bool in_set[P1_PTS], esc[P1_PTS];
    float cnt[P1_PTS], zr[P1_PTS], zi[P1_PTS];

    #pragma unroll
    for (int p = 0; p < P1_PTS; ++p) {
        const float c2 = ci[p] * ci[p];
        const float xm = cr[p] - 0.25f;
        const float q  = xm * xm + c2;
        const float xp = cr[p] + 1.0f;
        in_set[p] = (q * (q + xm) < 0.25f * c2) | (xp * xp + c2 < 0.0625f);
        esc[p] = false; cnt[p] = 0.0f; zr[p] = 0.0f; zi[p] = 0.0f;
    }

    #pragma unroll
    for (int i = 0; i < K1; ++i) {
        #pragma unroll
        for (int p = 0; p < P1_PTS; ++p) {
            float zr2 = zr[p] * zr[p] - zi[p] * zi[p] + cr[p]; // same as R1
            float zi2 = fmaf(2.0f * zr[p], zi[p], ci[p]);
            float mag = fmaf(zr2, zr2, zi2 * zi2);
            esc[p] |= (mag > 4.0f);
            if (!esc[p]) cnt[p] += 1.0f;
            zr[p] = zr2; zi[p] = zi2;
        }
    }

    unsigned int dist = 0;
    unsigned int smask = 0;
    #pragma unroll
    for (int p = 0; p < P1_PTS; ++p) {
        if (valid[p]) {
            if (in_set[p])   dist += 70u;                     // iters = 100
            else if (esc[p]) dist += (unsigned int)(29.0f - cnt[p]);
            else             smask |= (1u << p);
        }
    }

    // ---- survivor append (state-carrying): warp shfl-scan ----
    const int k = __popc(smask);
    int incl = k;
    #pragma unroll
    for (int off = 1; off < 32; off <<= 1) {
        int v = __shfl_up_sync(0xFFFFFFFFu, incl, off);
        if (lane >= off) incl += v;
    }
    const int excl = incl - k;
    const int warp_total = __shfl_sync(0xFFFFFFFFu, incl, 31);

    __shared__ unsigned int warp_base[P1_THREADS / 32];
    __shared__ unsigned int block_base;
    if (lane == 0) warp_base[wid] = (unsigned int)warp_total;
    __syncthreads();
    if (threadIdx.x == 0) {
        unsigned int tot = 0;
        #pragma unroll
        for (int w = 0; w < P1_THREADS / 32; ++w) {
            unsigned int c = warp_base[w];
            warp_base[w] = tot;
            tot += c;
        }
        block_base = tot ? atomicAdd(&g_ns1, tot) : 0u;
    }
    __syncthreads();

    if (smask) {
        unsigned int pos = block_base + warp_base[wid] + (unsigned int)excl;
        #pragma unroll
        for (int p = 0; p < P1_PTS; ++p)
            if (smask & (1u << p))
                g_st1[pos++] = make_float4(cr[p], ci[p], zr[p], zi[p]);
    }

    // ---- exact-integer distance reduction ----
    #pragma unroll
    for (int off = 16; off > 0; off >>= 1)
        dist += __shfl_down_sync(0xFFFFFFFFu, dist, off);

    __shared__ unsigned int warp_sums[P1_THREADS / 32];
    if (lane == 0) warp_sums[wid] = dist;
    __syncthreads();

    if (wid == 0) {
        unsigned int v = (lane < P1_THREADS / 32) ? warp_sums[lane] : 0u;
        #pragma unroll
        for (int off = 4; off > 0; off >>= 1)
            v += __shfl_down_sync(0xFFFFFFFFu, v, off);
        if (lane == 0 && v)
            atomicAdd(&g_sum, (unsigned long long)v);
    }
}

// ---------------------------------------------------------------- phase 2a
// continue iters 7..38 (32 iterations) from stored state
__global__ void __launch_bounds__(P2_THREADS) phase2a_kernel()
{
    const unsigned int total  = g_ns1;
    const unsigned int stride = gridDim.x * blockDim.x;
    const int lane = threadIdx.x & 31;
    const int wid  = threadIdx.x >> 5;

    unsigned int local = 0;

    for (unsigned int s = blockIdx.x * blockDim.x + threadIdx.x;
         __any_sync(0xFFFFFFFFu, s < total); s += stride) {
        const bool has = (s < total);
        const float4 st = has ? g_st1[s] : make_float4(10.f, 0.f, 10.f, 0.f);
        const float cr = st.x, ci = st.y;
        float zr = st.z, zi = st.w;
        float cnt = (float)K1;                  // 6: not escaped in 1..6
        bool esc = false;

        #pragma unroll 1
        for (int chunk = 0; chunk < 4; ++chunk) {
            #pragma unroll
            for (int j = 0; j < 8; ++j) {
                float zr2 = zr * zr - zi * zi + cr;        // same expr as R1
                float zi2 = fmaf(2.0f * zr, zi, ci);
                float mag = fmaf(zr2, zr2, zi2 * zi2);
                esc |= (mag > 4.0f);
                if (!esc) cnt += 1.0f;
                zr = zr2; zi = zi2;
            }
            if (__all_sync(0xFFFFFFFFu, esc)) break;
        }

        const bool surv = has & !esc;           // cnt == 38
        if (has & esc) local += (unsigned int)fabsf(cnt - 29.0f);

        // ---- state-carrying re-compaction ----
        const unsigned int mask = __ballot_sync(0xFFFFFFFFu, surv);
        if (mask) {
            unsigned int pos_base;
            if (lane == 0)
                pos_base = atomicAdd(&g_ns2, (unsigned int)__popc(mask));
            pos_base = __shfl_sync(0xFFFFFFFFu, pos_base, 0);
            if (surv) {
                unsigned int pos = pos_base
                    + (unsigned int)__popc(mask & ((1u << lane) - 1u));
                g_st2[pos] = make_float4(cr, ci, zr, zi);
            }
        }
    }

    // ---- reduction ----
    #pragma unroll
    for (int off = 16; off > 0; off >>= 1)
        local += __shfl_down_sync(0xFFFFFFFFu, local, off);

    __shared__ unsigned int warp_sums[P2_THREADS / 32];
    if (lane == 0) warp_sums[wid] = local;
    __syncthreads();

    if (wid == 0) {
        unsigned int v = (lane < P2_THREADS / 32) ? warp_sums[lane] : 0u;
        #pragma unroll
        for (int off = 4; off > 0; off >>= 1)
            v += __shfl_down_sync(0xFFFFFFFFu, v, off);
        if (lane == 0 && v)
            atomicAdd(&g_sum, (unsigned long long)v);
    }
}

// ---------------------------------------------------------------- phase 2b
// continue iters 39..102 (64; clamped) from stored state; fused finalize
__global__ void __launch_bounds__(P2_THREADS) phase2b_kernel(
    float* __restrict__ out, int n)
{
    const unsigned int total  = g_ns2;
    const unsigned int stride = gridDim.x * blockDim.x;
    const int lane = threadIdx.x & 31;
    const int wid  = threadIdx.x >> 5;

    unsigned int local = 0;

    for (unsigned int s = blockIdx.x * blockDim.x + threadIdx.x;
         __any_sync(0xFFFFFFFFu, s < total); s += stride) {
        const bool has = (s < total);
        const float4 st = has ? g_st2[s] : make_float4(10.f, 0.f, 10.f, 0.f);
        const float cr = st.x, ci = st.y;
        float zr = st.z, zi = st.w;
        float cnt = 38.0f;
        bool esc = false;

        #pragma unroll 1
        for (int chunk = 0; chunk < 8; ++chunk) {
            #pragma unroll
            for (int j = 0; j < 8; ++j) {
                float zr2 = zr * zr - zi * zi + cr;        // same expr as R1
                float zi2 = fmaf(2.0f * zr, zi, ci);
                float mag = fmaf(zr2, zr2, zi2 * zi2);
                esc |= (mag > 4.0f);
                if (!esc) cnt += 1.0f;
                zr = zr2; zi = zi2;
            }
            if (__all_sync(0xFFFFFFFFu, esc)) break;
        }

        if (has) {
            // escape at iter cnt+1 <= 100 -> |cnt-29| ; not escaped by 100
            // (cnt >= 100, incl. overrun iters 101/102) -> dist 70
            unsigned int d = (cnt > 99.0f) ? 70u
                                           : (unsigned int)fabsf(cnt - 29.0f);
            local += d;
        }
    }

    // ---- reduction ----
    #pragma unroll
    for (int off = 16; off > 0; off >>= 1)
        local += __shfl_down_sync(0xFFFFFFFFu, local, off);

    __shared__ unsigned int warp_sums[P2_THREADS / 32];
    if (lane == 0) warp_sums[wid] = local;
    __syncthreads();

    if (wid == 0) {
        unsigned int v = (lane < P2_THREADS / 32) ? warp_sums[lane] : 0u;
        #pragma unroll
        for (int off = 4; off > 0; off >>= 1)
            v += __shfl_down_sync(0xFFFFFFFFu, v, off);
        if (lane == 0 && v)
            atomicAdd(&g_sum, (unsigned long long)v);
    }

    // ---- last-block finalize ----
    if (threadIdx.x == 0) {
        __threadfence();
        unsigned int ticket = atomicAdd(&g_done, 1u);
        if (ticket == gridDim.x - 1u) {
            __threadfence();
            double sum = (double)g_sum;
            out[0] = (float)(sum * (0.1 / 30.0) / (double)n);
            g_sum = 0ULL;          // reset for next graph replay
            g_ns1 = 0u;
            g_ns2 = 0u;
            g_done = 0u;
        }
    }
}

extern "C" void kernel_launch(void* const* d_in, const int* in_sizes, int n_in,
                              void* d_out, int out_size)
{
    const float* c_real = (const float*)d_in[0];
    const float* c_imag = (const float*)d_in[1];
    float* out = (float*)d_out;
    const int n = in_sizes[0];

    const int pts_per_block = P1_THREADS * P1_PTS;
    const int p1_blocks = (n + pts_per_block - 1) / pts_per_block;
    phase1_kernel<<<p1_blocks, P1_THREADS>>>(c_real, c_imag, n);

    phase2a_kernel<<<P2A_BLOCKS, P2_THREADS>>>();
    phase2b_kernel<<<P2B_BLOCKS, P2_THREADS>>>(out, n);
}

// round 8
// speedup vs baseline: 1.1240x; 1.1240x over previous
#include <cuda_runtime.h>

// Mandelbrot boundary-proximity loss. R8: state-carrying pipeline with
// minimal live state (index + float2{zr,zi}; cr,ci re-gathered from inputs).
//   phase 1 : all N, K1=12, cardioid/bulb filter, 4 pts/thread,
//             __launch_bounds__(256,7) pins regs<=36 (R7 lost occupancy).
//   phase 2a: survivors continue iters 13..44 from stored z; alive re-compact.
//   phase 2b: iters 45..100 (exactly 56); esc&&cnt<=99 -> |cnt-29| else 70;
//             fused last-block finalize.
// Continuation == same float sequence as replay => classification identical
// to validated R1/R6 arithmetic. Cycle check omitted (value-neutral).
// Reduction: exact integer ULL sum => deterministic.

#define NMAX 8388608
#define K1 12
#define P1_THREADS 256
#define P1_PTS 4
#define P2A_BLOCKS 4096
#define P2B_BLOCKS 2048
#define P2_THREADS 256

__device__ unsigned long long g_sum;   // zero-init at load
__device__ unsigned int g_ns1;
__device__ unsigned int g_ns2;
__device__ unsigned int g_done;
__device__ unsigned int g_idx1[NMAX];
__device__ float2       g_z1[NMAX];    // z after iter 12
__device__ unsigned int g_idx2[NMAX];
__device__ float2       g_z2[NMAX];    // z after iter 44

// ---------------------------------------------------------------- phase 1
__global__ void __launch_bounds__(P1_THREADS, 7) phase1_kernel(
    const float* __restrict__ c_real,
    const float* __restrict__ c_imag,
    int n)
{
    const int tid  = blockIdx.x * P1_THREADS + threadIdx.x;
    const int base = tid * P1_PTS;
    const int lane = threadIdx.x & 31;
    const int wid  = threadIdx.x >> 5;

    float cr[P1_PTS], ci[P1_PTS];
    bool valid[P1_PTS];

    if (base + P1_PTS - 1 < n) {
        const float4 r4 = *reinterpret_cast<const float4*>(c_real + base);
        const float4 i4 = *reinterpret_cast<const float4*>(c_imag + base);
        cr[0] = r4.x; cr[1] = r4.y; cr[2] = r4.z; cr[3] = r4.w;
        ci[0] = i4.x; ci[1] = i4.y; ci[2] = i4.z; ci[3] = i4.w;
        #pragma unroll
        for (int p = 0; p < P1_PTS; ++p) valid[p] = true;
    } else {
        #pragma unroll
        for (int p = 0; p < P1_PTS; ++p) {
            valid[p] = (base + p) < n;
            cr[p] = valid[p] ? c_real[base + p] : 10.0f;  // dummy escapes fast
            ci[p] = valid[p] ? c_imag[base + p] : 0.0f;
        }
    }

    bool in_set[P1_PTS], esc[P1_PTS];
    float cnt[P1_PTS], zr[P1_PTS], zi[P1_PTS];

    #pragma unroll
    for (int p = 0; p < P1_PTS; ++p) {
        const float c2 = ci[p] * ci[p];
        const float xm = cr[p] - 0.25f;
        const float q  = xm * xm + c2;
        const float xp = cr[p] + 1.0f;
        in_set[p] = (q * (q + xm) < 0.25f * c2) | (xp * xp + c2 < 0.0625f);
        esc[p] = false; cnt[p] = 0.0f; zr[p] = 0.0f; zi[p] = 0.0f;
    }

    #pragma unroll
    for (int i = 0; i < K1; ++i) {
        #pragma unroll
        for (int p = 0; p < P1_PTS; ++p) {
            float zr2 = zr[p] * zr[p] - zi[p] * zi[p] + cr[p]; // same as R1
            float zi2 = fmaf(2.0f * zr[p], zi[p], ci[p]);
            float mag = fmaf(zr2, zr2, zi2 * zi2);
            esc[p] |= (mag > 4.0f);          // sticky; NaN-safe post-escape
            if (!esc[p]) cnt[p] += 1.0f;
            zr[p] = zr2; zi[p] = zi2;
        }
    }

    unsigned int dist = 0;
    unsigned int smask = 0;
    #pragma unroll
    for (int p = 0; p < P1_PTS; ++p) {
        if (valid[p]) {
            if (in_set[p])   dist += 70u;                     // iters = 100
            else if (esc[p]) dist += (unsigned int)(29.0f - cnt[p]);
            else             smask |= (1u << p);
        }
    }

    // ---- survivor append: warp shfl-scan (index + z-state) ----
    const int k = __popc(smask);
    int incl = k;
    #pragma unroll
    for (int off = 1; off < 32; off <<= 1) {
        int v = __shfl_up_sync(0xFFFFFFFFu, incl, off);
        if (lane >= off) incl += v;
    }
    const int excl = incl - k;
    const int warp_total = __shfl_sync(0xFFFFFFFFu, incl, 31);

    __shared__ unsigned int warp_base[P1_THREADS / 32];
    __shared__ unsigned int block_base;
    if (lane == 0) warp_base[wid] = (unsigned int)warp_total;
    __syncthreads();
    if (threadIdx.x == 0) {
        unsigned int tot = 0;
        #pragma unroll
        for (int w = 0; w < P1_THREADS / 32; ++w) {
            unsigned int c = warp_base[w];
            warp_base[w] = tot;
            tot += c;
        }
        block_base = tot ? atomicAdd(&g_ns1, tot) : 0u;
    }
    __syncthreads();

    if (smask) {
        unsigned int pos = block_base + warp_base[wid] + (unsigned int)excl;
        #pragma unroll
        for (int p = 0; p < P1_PTS; ++p)
            if (smask & (1u << p)) {
                g_idx1[pos] = (unsigned int)(base + p);
                g_z1[pos]   = make_float2(zr[p], zi[p]);
                ++pos;
            }
    }

    // ---- exact-integer distance reduction ----
    #pragma unroll
    for (int off = 16; off > 0; off >>= 1)
        dist += __shfl_down_sync(0xFFFFFFFFu, dist, off);

    __shared__ unsigned int warp_sums[P1_THREADS / 32];
    if (lane == 0) warp_sums[wid] = dist;
    __syncthreads();

    if (wid == 0) {
        unsigned int v = (lane < P1_THREADS / 32) ? warp_sums[lane] : 0u;
        #pragma unroll
        for (int off = 4; off > 0; off >>= 1)
            v += __shfl_down_sync(0xFFFFFFFFu, v, off);
        if (lane == 0 && v)
            atomicAdd(&g_sum, (unsigned long long)v);
    }
}

// ---------------------------------------------------------------- phase 2a
// continue iters 13..44 (32) from stored z; re-compact alive with state
__global__ void __launch_bounds__(P2_THREADS) phase2a_kernel(
    const float* __restrict__ c_real,
    const float* __restrict__ c_imag)
{
    const unsigned int total  = g_ns1;
    const unsigned int stride = gridDim.x * blockDim.x;
    const int lane = threadIdx.x & 31;
    const int wid  = threadIdx.x >> 5;

    unsigned int local = 0;

    for (unsigned int s = blockIdx.x * blockDim.x + threadIdx.x;
         __any_sync(0xFFFFFFFFu, s < total); s += stride) {
        const bool has = (s < total);
        const unsigned int idx = has ? g_idx1[s] : 0u;
        const float2 z0 = has ? g_z1[s] : make_float2(10.0f, 0.0f);
        const float cr = has ? __ldg(c_real + idx) : 10.0f;  // dummy escapes
        const float ci = has ? __ldg(c_imag + idx) : 0.0f;
        float zr = z0.x, zi = z0.y;
        float cnt = (float)K1;            // 12: unescaped through iter 12
        bool esc = false;

        #pragma unroll 1
        for (int chunk = 0; chunk < 4; ++chunk) {
            #pragma unroll
            for (int j = 0; j < 8; ++j) {
                float zr2 = zr * zr - zi * zi + cr;        // same expr as R1
                float zi2 = fmaf(2.0f * zr, zi, ci);
                float mag = fmaf(zr2, zr2, zi2 * zi2);
                esc |= (mag > 4.0f);
                if (!esc) cnt += 1.0f;
                zr = zr2; zi = zi2;
            }
            if (__all_sync(0xFFFFFFFFu, esc)) break;
        }

        if (has & esc) local += (unsigned int)fabsf(cnt - 29.0f);

        const bool surv = has & !esc;     // cnt == 44
        const unsigned int mask = __ballot_sync(0xFFFFFFFFu, surv);
        if (mask) {
            unsigned int pos_base;
            if (lane == 0)
                pos_base = atomicAdd(&g_ns2, (unsigned int)__popc(mask));
            pos_base = __shfl_sync(0xFFFFFFFFu, pos_base, 0);
            if (surv) {
                unsigned int pos = pos_base
                    + (unsigned int)__popc(mask & ((1u << lane) - 1u));
                g_idx2[pos] = idx;
                g_z2[pos]   = make_float2(zr, zi);
            }
        }
    }

    #pragma unroll
    for (int off = 16; off > 0; off >>= 1)
        local += __shfl_down_sync(0xFFFFFFFFu, local, off);

    __shared__ unsigned int warp_sums[P2_THREADS / 32];
    if (lane == 0) warp_sums[wid] = local;
    __syncthreads();

    if (wid == 0) {
        unsigned int v = (lane < P2_THREADS / 32) ? warp_sums[lane] : 0u;
        #pragma unroll
        for (int off = 4; off > 0; off >>= 1)
            v += __shfl_down_sync(0xFFFFFFFFu, v, off);
        if (lane == 0 && v)
            atomicAdd(&g_sum, (unsigned long long)v);
    }
}

// ---------------------------------------------------------------- phase 2b
// continue iters 45..100 (exactly 56 = 7x8); fused finalize
__global__ void __launch_bounds__(P2_THREADS) phase2b_kernel(
    const float* __restrict__ c_real,
    const float* __restrict__ c_imag,
    float* __restrict__ out, int n)
{
    const unsigned int total  = g_ns2;
    const unsigned int stride = gridDim.x * blockDim.x;
    const int lane = threadIdx.x & 31;
    const int wid  = threadIdx.x >> 5;

    unsigned int local = 0;

    for (unsigned int s = blockIdx.x * blockDim.x + threadIdx.x;
         __any_sync(0xFFFFFFFFu, s < total); s += stride) {
        const bool has = (s < total);
        const unsigned int idx = has ? g_idx2[s] : 0u;
        const float2 z0 = has ? g_z2[s] : make_float2(10.0f, 0.0f);
        const float cr = has ? __ldg(c_real + idx) : 10.0f;
        const float ci = has ? __ldg(c_imag + idx) : 0.0f;
        float zr = z0.x, zi = z0.y;
        float cnt = 44.0f;                // unescaped through iter 44
        bool esc = false;

        #pragma unroll 1
        for (int chunk = 0; chunk < 7; ++chunk) {
            #pragma unroll
            for (int j = 0; j < 8; ++j) {
                float zr2 = zr * zr - zi * zi + cr;        // same expr as R1
                float zi2 = fmaf(2.0f * zr, zi, ci);
                float mag = fmaf(zr2, zr2, zi2 * zi2);
                esc |= (mag > 4.0f);
                if (!esc) cnt += 1.0f;
                zr = zr2; zi = zi2;
            }
            if (__all_sync(0xFFFFFFFFu, esc)) break;
        }

        if (has) {
            // escape at iter cnt+1 <= 100  -> |cnt-29|
            // unescaped through 100 (cnt==100) -> 70 (== escape@100 case)
            unsigned int d = (esc && cnt <= 99.0f)
                           ? (unsigned int)fabsf(cnt - 29.0f) : 70u;
            local += d;
        }
    }

    #pragma unroll
    for (int off = 16; off > 0; off >>= 1)
        local += __shfl_down_sync(0xFFFFFFFFu, local, off);

    __shared__ unsigned int warp_sums[P2_THREADS / 32];
    if (lane == 0) warp_sums[wid] = local;
    __syncthreads();

    if (wid == 0) {
        unsigned int v = (lane < P2_THREADS / 32) ? warp_sums[lane] : 0u;
        #pragma unroll
        for (int off = 4; off > 0; off >>= 1)
            v += __shfl_down_sync(0xFFFFFFFFu, v, off);
        if (lane == 0 && v)
            atomicAdd(&g_sum, (unsigned long long)v);
    }

    // ---- last-block finalize ----
    if (threadIdx.x == 0) {
        __threadfence();
        unsigned int ticket = atomicAdd(&g_done, 1u);
        if (ticket == gridDim.x - 1u) {
            __threadfence();
            double sum = (double)g_sum;
            out[0] = (float)(sum * (0.1 / 30.0) / (double)n);
            g_sum = 0ULL;          // reset for next graph replay
            g_ns1 = 0u;
            g_ns2 = 0u;
            g_done = 0u;
        }
    }
}

extern "C" void kernel_launch(void* const* d_in, const int* in_sizes, int n_in,
                              void* d_out, int out_size)
{
    const float* c_real = (const float*)d_in[0];
    const float* c_imag = (const float*)d_in[1];
    float* out = (float*)d_out;
    const int n = in_sizes[0];

    const int pts_per_block = P1_THREADS * P1_PTS;
    const int p1_blocks = (n + pts_per_block - 1) / pts_per_block;
    phase1_kernel<<<p1_blocks, P1_THREADS>>>(c_real, c_imag, n);

    phase2a_kernel<<<P2A_BLOCKS, P2_THREADS>>>(c_real, c_imag);
    phase2b_kernel<<<P2B_BLOCKS, P2_THREADS>>>(c_real, c_imag, out, n);
}

// round 9
// speedup vs baseline: 1.1682x; 1.0393x over previous
#include <cuda_runtime.h>

// Mandelbrot boundary-proximity loss. R9: state-carrying 3-stage pipeline,
// fused p1 epilogue (single packed scan gives dist-reduction AND compaction
// offsets), FFMA-restructured inner loop (8 instr/pt/iter), K1=10,
// 2a = iters 11..42, 2b = iters 43..~100 (overrun-clamped, exact), with
// dual-end partition of 2b input by |z42|^2 so escaper warps vote-exit early.
// Reduction: exact integer ULL sum => deterministic.

#define NMAX 8388608
#define K1 10
#define B2 42
#define P1_THREADS 256
#define P1_PTS 4
#define P2A_BLOCKS 2048
#define P2B_BLOCKS 1024
#define P2_THREADS 256

__device__ unsigned long long g_sum;   // zero-init at load
__device__ unsigned int g_ns1;
__device__ unsigned int g_ns2_lo;      // front bucket (likely escapers)
__device__ unsigned int g_ns2_hi;      // back bucket (likely in-set)
__device__ unsigned int g_done;
__device__ unsigned int g_idx1[NMAX];
__device__ float2       g_z1[NMAX];    // z after iter K1
__device__ unsigned int g_idx2[NMAX];
__device__ float2       g_z2[NMAX];    // z after iter B2

// ---------------------------------------------------------------- phase 1
__global__ void __launch_bounds__(P1_THREADS, 7) phase1_kernel(
    const float* __restrict__ c_real,
    const float* __restrict__ c_imag,
    int n)
{
    const int tid  = blockIdx.x * P1_THREADS + threadIdx.x;
    const int base = tid * P1_PTS;
    const int lane = threadIdx.x & 31;
    const int wid  = threadIdx.x >> 5;

    float cr[P1_PTS], ci[P1_PTS];
    bool valid[P1_PTS];

    if (base + P1_PTS - 1 < n) {
        const float4 r4 = *reinterpret_cast<const float4*>(c_real + base);
        const float4 i4 = *reinterpret_cast<const float4*>(c_imag + base);
        cr[0] = r4.x; cr[1] = r4.y; cr[2] = r4.z; cr[3] = r4.w;
        ci[0] = i4.x; ci[1] = i4.y; ci[2] = i4.z; ci[3] = i4.w;
        #pragma unroll
        for (int p = 0; p < P1_PTS; ++p) valid[p] = true;
    } else {
        #pragma unroll
        for (int p = 0; p < P1_PTS; ++p) {
            valid[p] = (base + p) < n;
            cr[p] = valid[p] ? c_real[base + p] : 10.0f;  // dummy escapes fast
            ci[p] = valid[p] ? c_imag[base + p] : 0.0f;
        }
    }

    bool in_set[P1_PTS], esc[P1_PTS];
    float cnt[P1_PTS], zr[P1_PTS], zi[P1_PTS];

    #pragma unroll
    for (int p = 0; p < P1_PTS; ++p) {
        const float c2 = ci[p] * ci[p];
        const float xm = cr[p] - 0.25f;
        const float q  = xm * xm + c2;
        const float xp = cr[p] + 1.0f;
        in_set[p] = (q * (q + xm) < 0.25f * c2) | (xp * xp + c2 < 0.0625f);
        esc[p] = false; cnt[p] = 0.0f; zr[p] = 0.0f; zi[p] = 0.0f;
    }

    #pragma unroll
    for (int i = 0; i < K1; ++i) {
        #pragma unroll
        for (int p = 0; p < P1_PTS; ++p) {
            float t   = fmaf(zi[p], -zi[p], cr[p]);        // cr - zi^2
            float zr2 = fmaf(zr[p],  zr[p], t);            // zr^2 + (cr - zi^2)
            float zi2 = fmaf(zr[p] + zr[p], zi[p], ci[p]);
            float mag = fmaf(zr2, zr2, zi2 * zi2);
            esc[p] |= (mag > 4.0f);          // sticky; NaN-safe post-escape
            if (!esc[p]) cnt[p] += 1.0f;
            zr[p] = zr2; zi[p] = zi2;
        }
    }

    unsigned int dist = 0;
    unsigned int smask = 0;
    #pragma unroll
    for (int p = 0; p < P1_PTS; ++p) {
        if (valid[p]) {
            if (in_set[p])   dist += 70u;                  // iters = 100
            else if (esc[p]) dist += (unsigned int)(29.0f - cnt[p]);
            else             smask |= (1u << p);
        }
    }

    // ---- fused epilogue: one packed scan = dist reduction + compaction ----
    // packed: survivor count in bits [24:32), dist in bits [0:24)
    const unsigned int k = (unsigned int)__popc(smask);
    const unsigned int packed = (k << 24) | dist;
    unsigned int incl = packed;
    #pragma unroll
    for (int off = 1; off < 32; off <<= 1) {
        unsigned int v = __shfl_up_sync(0xFFFFFFFFu, incl, off);
        if (lane >= off) incl += v;
    }
    const unsigned int excl_cnt = (incl - packed) >> 24;

    __shared__ unsigned int warp_pack[P1_THREADS / 32];
    __shared__ unsigned int warp_cbase[P1_THREADS / 32];
    __shared__ unsigned int blk_base;
    if (lane == 31) warp_pack[wid] = incl;     // warp totals (count|dist)
    __syncthreads();

    if (threadIdx.x == 0) {
        unsigned int cnt_tot = 0, dist_tot = 0;
        #pragma unroll
        for (int w = 0; w < P1_THREADS / 32; ++w) {
            unsigned int pk = warp_pack[w];
            warp_cbase[w] = cnt_tot;
            cnt_tot  += pk >> 24;
            dist_tot += pk & 0xFFFFFFu;
        }
        blk_base = cnt_tot ? atomicAdd(&g_ns1, cnt_tot) : 0u;
        if (dist_tot) atomicAdd(&g_sum, (unsigned long long)dist_tot);
    }
    __syncthreads();

    if (smask) {
        unsigned int pos = blk_base + warp_cbase[wid] + excl_cnt;
        #pragma unroll
        for (int p = 0; p < P1_PTS; ++p)
            if (smask & (1u << p)) {
                g_idx1[pos] = (unsigned int)(base + p);
                g_z1[pos]   = make_float2(zr[p], zi[p]);
                ++pos;
            }
    }
}

// ---------------------------------------------------------------- phase 2a
// continue iters K1+1..B2 (32) from stored z; partition alive by |z|^2
__global__ void __launch_bounds__(P2_THREADS) phase2a_kernel(
    const float* __restrict__ c_real,
    const float* __restrict__ c_imag)
{
    const unsigned int total  = g_ns1;
    const unsigned int stride = gridDim.x * blockDim.x;
    const int lane = threadIdx.x & 31;
    const int wid  = threadIdx.x >> 5;

    unsigned int local = 0;

    for (unsigned int s = blockIdx.x * blockDim.x + threadIdx.x;
         __any_sync(0xFFFFFFFFu, s < total); s += stride) {
        const bool has = (s < total);
        const unsigned int idx = has ? g_idx1[s] : 0u;
        const float2 z0 = has ? g_z1[s] : make_float2(10.0f, 0.0f);
        const float cr = has ? __ldg(c_real + idx) : 10.0f;  // dummy escapes
        const float ci = has ? __ldg(c_imag + idx) : 0.0f;
        float zr = z0.x, zi = z0.y;
        float cnt = (float)K1;
        bool esc = false;

        #pragma unroll 1
        for (int chunk = 0; chunk < (B2 - K1) / 8; ++chunk) {
            #pragma unroll
            for (int j = 0; j < 8; ++j) {
                float t   = fmaf(zi, -zi, cr);
                float zr2 = fmaf(zr,  zr, t);
                float zi2 = fmaf(zr + zr, zi, ci);
                float mag = fmaf(zr2, zr2, zi2 * zi2);
                esc |= (mag > 4.0f);
                if (!esc) cnt += 1.0f;
                zr = zr2; zi = zi2;
            }
            if (__all_sync(0xFFFFFFFFu, esc)) break;
        }

        if (has & esc) local += (unsigned int)fabsf(cnt - 29.0f);

        // ---- dual-end partitioned re-compaction ----
        const bool surv = has & !esc;                      // cnt == B2
        const float magf = fmaf(zr, zr, zi * zi);
        const bool likely_esc = surv && (magf > 2.0f);
        const bool likely_set = surv && !(magf > 2.0f);

        const unsigned int maskA = __ballot_sync(0xFFFFFFFFu, likely_esc);
        if (maskA) {
            unsigned int b;
            if (lane == 0) b = atomicAdd(&g_ns2_lo, (unsigned int)__popc(maskA));
            b = __shfl_sync(0xFFFFFFFFu, b, 0);
            if (likely_esc) {
                unsigned int pos = b
                    + (unsigned int)__popc(maskA & ((1u << lane) - 1u));
                g_idx2[pos] = idx;
                g_z2[pos]   = make_float2(zr, zi);
            }
        }
        const unsigned int maskB = __ballot_sync(0xFFFFFFFFu, likely_set);
        if (maskB) {
            unsigned int b;
            if (lane == 0) b = atomicAdd(&g_ns2_hi, (unsigned int)__popc(maskB));
            b = __shfl_sync(0xFFFFFFFFu, b, 0);
            if (likely_set) {
                unsigned int pos = (unsigned int)NMAX - 1u
                    - (b + (unsigned int)__popc(maskB & ((1u << lane) - 1u)));
                g_idx2[pos] = idx;
                g_z2[pos]   = make_float2(zr, zi);
            }
        }
    }

    #pragma unroll
    for (int off = 16; off > 0; off >>= 1)
        local += __shfl_down_sync(0xFFFFFFFFu, local, off);

    __shared__ unsigned int warp_sums[P2_THREADS / 32];
    if (lane == 0) warp_sums[wid] = local;
    __syncthreads();

    if (wid == 0) {
        unsigned int v = (lane < P2_THREADS / 32) ? warp_sums[lane] : 0u;
        #pragma unroll
        for (int off = 4; off > 0; off >>= 1)
            v += __shfl_down_sync(0xFFFFFFFFu, v, off);
        if (lane == 0 && v)
            atomicAdd(&g_sum, (unsigned long long)v);
    }
}

// ---------------------------------------------------------------- phase 2b
// continue iters B2+1.. (64, overrun-clamped exactly); fused finalize
__global__ void __launch_bounds__(P2_THREADS) phase2b_kernel(
    const float* __restrict__ c_real,
    const float* __restrict__ c_imag,
    float* __restrict__ out, int n)
{
    const unsigned int lo = g_ns2_lo;
    const unsigned int hi = g_ns2_hi;
    const unsigned int total  = lo + hi;
    const unsigned int stride = gridDim.x * blockDim.x;
    const int lane = threadIdx.x & 31;
    const int wid  = threadIdx.x >> 5;

    unsigned int local = 0;

    for (unsigned int s = blockIdx.x * blockDim.x + threadIdx.x;
         __any_sync(0xFFFFFFFFu, s < total); s += stride) {
        const bool has = (s < total);
        const unsigned int j = (s < lo) ? s
                             : (unsigned int)NMAX - 1u - (s - lo);
        const unsigned int idx = has ? g_idx2[j] : 0u;
        const float2 z0 = has ? g_z2[j] : make_float2(10.0f, 0.0f);
        const float cr = has ? __ldg(c_real + idx) : 10.0f;
        const float ci = has ? __ldg(c_imag + idx) : 0.0f;
        float zr = z0.x, zi = z0.y;
        float cnt = (float)B2;
        bool esc = false;

        #pragma unroll 1
        for (int chunk = 0; chunk < 8; ++chunk) {
            #pragma unroll
            for (int jj = 0; jj < 8; ++jj) {
                float t   = fmaf(zi, -zi, cr);
                float zr2 = fmaf(zr,  zr, t);
                float zi2 = fmaf(zr + zr, zi, ci);
                float mag = fmaf(zr2, zr2, zi2 * zi2);
                esc |= (mag > 4.0f);
                if (!esc) cnt += 1.0f;
                zr = zr2; zi = zi2;
            }
            if (__all_sync(0xFFFFFFFFu, esc)) break;
        }

        if (has) {
            // escape at iter cnt+1 <= 100 -> |cnt-29|; otherwise (cnt>99:
            // escaped past 100 or never) -> 70, exactly matching the
            // reference cap at 100 iterations.
            unsigned int d = (esc && cnt <= 99.0f)
                           ? (unsigned int)fabsf(cnt - 29.0f) : 70u;
            local += d;
        }
    }

    #pragma unroll
    for (int off = 16; off > 0; off >>= 1)
        local += __shfl_down_sync(0xFFFFFFFFu, local, off);

    __shared__ unsigned int warp_sums[P2_THREADS / 32];
    if (lane == 0) warp_sums[wid] = local;
    __syncthreads();

    if (wid == 0) {
        unsigned int v = (lane < P2_THREADS / 32) ? warp_sums[lane] : 0u;
        #pragma unroll
        for (int off = 4; off > 0; off >>= 1)
            v += __shfl_down_sync(0xFFFFFFFFu, v, off);
        if (lane == 0 && v)
            atomicAdd(&g_sum, (unsigned long long)v);
    }

    // ---- last-block finalize ----
    if (threadIdx.x == 0) {
        __threadfence();
        unsigned int ticket = atomicAdd(&g_done, 1u);
        if (ticket == gridDim.x - 1u) {
            __threadfence();
            double sum = (double)g_sum;
            out[0] = (float)(sum * (0.1 / 30.0) / (double)n);
            g_sum = 0ULL;          // reset for next graph replay
            g_ns1 = 0u;
            g_ns2_lo = 0u;
            g_ns2_hi = 0u;
            g_done = 0u;
        }
    }
}

extern "C" void kernel_launch(void* const* d_in, const int* in_sizes, int n_in,
                              void* d_out, int out_size)
{
    const float* c_real = (const float*)d_in[0];
    const float* c_imag = (const float*)d_in[1];
    float* out = (float*)d_out;
    const int n = in_sizes[0];

    const int pts_per_block = P1_THREADS * P1_PTS;
    const int p1_blocks = (n + pts_per_block - 1) / pts_per_block;
    phase1_kernel<<<p1_blocks, P1_THREADS>>>(c_real, c_imag, n);

    phase2a_kernel<<<P2A_BLOCKS, P2_THREADS>>>(c_real, c_imag);
    phase2b_kernel<<<P2B_BLOCKS, P2_THREADS>>>(c_real, c_imag, out, n);
}

// round 10
// speedup vs baseline: 1.2347x; 1.0569x over previous
#include <cuda_runtime.h>

// Mandelbrot boundary-proximity loss. R10: self-contained state pipeline.
//   phase 1 : all N, K1=10, cardioid + period-2 + period-3(inscribed) filter,
//             4 pts/thread, fused packed-scan epilogue; survivors stored as
//             float4{cr,ci,zr,zi} (c re-loaded from L1-hot input in epilogue
//             so register liveness stays at R9 levels).
//   phase 2a: iters 11..42 from stored state (NO gathers); alive points
//             dual-end partitioned by |z42|^2 into escaper/in-set buckets.
//   phase 2b: iters 43..~106 (overrun clamped exactly at 100); fused finalize.
// Cycle check omitted (value-neutral: in_cycle => iters=100 == exhaustion).
// Reduction: exact integer ULL sum => deterministic.

#define NMAX 8388608
#define K1 10
#define B2 42
#define P1_THREADS 256
#define P1_PTS 4
#define P2A_BLOCKS 4096
#define P2B_BLOCKS 1024
#define P2_THREADS 256

__device__ unsigned long long g_sum;   // zero-init at load
__device__ unsigned int g_ns1;
__device__ unsigned int g_ns2_lo;      // front bucket (likely escapers)
__device__ unsigned int g_ns2_hi;      // back bucket (likely in-set)
__device__ unsigned int g_done;
__device__ float4 g_st1[NMAX];         // {cr,ci,zr,zi} after iter K1
__device__ float4 g_st2[NMAX];         // {cr,ci,zr,zi} after iter B2

// ---------------------------------------------------------------- phase 1
__global__ void __launch_bounds__(P1_THREADS, 7) phase1_kernel(
    const float* __restrict__ c_real,
    const float* __restrict__ c_imag,
    int n)
{
    const int tid  = blockIdx.x * P1_THREADS + threadIdx.x;
    const int base = tid * P1_PTS;
    const int lane = threadIdx.x & 31;
    const int wid  = threadIdx.x >> 5;

    float cr[P1_PTS], ci[P1_PTS];
    bool valid[P1_PTS];

    if (base + P1_PTS - 1 < n) {
        const float4 r4 = *reinterpret_cast<const float4*>(c_real + base);
        const float4 i4 = *reinterpret_cast<const float4*>(c_imag + base);
        cr[0] = r4.x; cr[1] = r4.y; cr[2] = r4.z; cr[3] = r4.w;
        ci[0] = i4.x; ci[1] = i4.y; ci[2] = i4.z; ci[3] = i4.w;
        #pragma unroll
        for (int p = 0; p < P1_PTS; ++p) valid[p] = true;
    } else {
        #pragma unroll
        for (int p = 0; p < P1_PTS; ++p) {
            valid[p] = (base + p) < n;
            cr[p] = valid[p] ? c_real[base + p] : 10.0f;  // dummy escapes fast
            ci[p] = valid[p] ? c_imag[base + p] : 0.0f;
        }
    }

    bool in_set[P1_PTS], esc[P1_PTS];
    float cnt[P1_PTS], zr[P1_PTS], zi[P1_PTS];

    #pragma unroll
    for (int p = 0; p < P1_PTS; ++p) {
        // analytic in-set: main cardioid, period-2 bulb, period-3 bulbs
        // (period-3: inscribed circles r=0.090 < true ~0.0963 at
        //  c = -0.1226 +/- 0.7449i; one-sided safe)
        const float c2 = ci[p] * ci[p];
        const float xm = cr[p] - 0.25f;
        const float q  = xm * xm + c2;
        const float xp = cr[p] + 1.0f;
        const float ax = cr[p] + 0.1226f;
        const float ay = fabsf(ci[p]) - 0.7449f;
        in_set[p] = (q * (q + xm) < 0.25f * c2)
                  | (xp * xp + c2 < 0.0625f)
                  | (fmaf(ax, ax, ay * ay) < 0.0081f);
        esc[p] = false; cnt[p] = 0.0f; zr[p] = 0.0f; zi[p] = 0.0f;
    }

    #pragma unroll
    for (int i = 0; i < K1; ++i) {
        #pragma unroll
        for (int p = 0; p < P1_PTS; ++p) {
            float t   = fmaf(zi[p], -zi[p], cr[p]);        // cr - zi^2
            float zr2 = fmaf(zr[p],  zr[p], t);            // zr^2 + (cr - zi^2)
            float zi2 = fmaf(zr[p] + zr[p], zi[p], ci[p]);
            float mag = fmaf(zr2, zr2, zi2 * zi2);
            esc[p] |= (mag > 4.0f);          // sticky; NaN-safe post-escape
            if (!esc[p]) cnt[p] += 1.0f;
            zr[p] = zr2; zi[p] = zi2;
        }
    }

    unsigned int dist = 0;
    unsigned int smask = 0;
    #pragma unroll
    for (int p = 0; p < P1_PTS; ++p) {
        if (valid[p]) {
            if (in_set[p])   dist += 70u;                  // iters = 100
            else if (esc[p]) dist += (unsigned int)(29.0f - cnt[p]);
            else             smask |= (1u << p);
        }
    }

    // ---- fused epilogue: one packed scan = dist reduction + compaction ----
    const unsigned int k = (unsigned int)__popc(smask);
    const unsigned int packed = (k << 24) | dist;
    unsigned int incl = packed;
    #pragma unroll
    for (int off = 1; off < 32; off <<= 1) {
        unsigned int v = __shfl_up_sync(0xFFFFFFFFu, incl, off);
        if (lane >= off) incl += v;
    }
    const unsigned int excl_cnt = (incl - packed) >> 24;

    __shared__ unsigned int warp_pack[P1_THREADS / 32];
    __shared__ unsigned int warp_cbase[P1_THREADS / 32];
    __shared__ unsigned int blk_base;
    if (lane == 31) warp_pack[wid] = incl;
    __syncthreads();

    if (threadIdx.x == 0) {
        unsigned int cnt_tot = 0, dist_tot = 0;
        #pragma unroll
        for (int w = 0; w < P1_THREADS / 32; ++w) {
            unsigned int pk = warp_pack[w];
            warp_cbase[w] = cnt_tot;
            cnt_tot  += pk >> 24;
            dist_tot += pk & 0xFFFFFFu;
        }
        blk_base = cnt_tot ? atomicAdd(&g_ns1, cnt_tot) : 0u;
        if (dist_tot) atomicAdd(&g_sum, (unsigned long long)dist_tot);
    }
    __syncthreads();

    if (smask) {
        unsigned int pos = blk_base + warp_cbase[wid] + excl_cnt;
        #pragma unroll
        for (int p = 0; p < P1_PTS; ++p)
            if (smask & (1u << p)) {
                // c re-loaded (L1-hot) instead of kept live through the scan
                g_st1[pos] = make_float4(c_real[base + p], c_imag[base + p],
                                         zr[p], zi[p]);
                ++pos;
            }
    }
}

// ---------------------------------------------------------------- phase 2a
// continue iters K1+1..B2 (32) from stored state; dual-end partition alive
__global__ void __launch_bounds__(P2_THREADS) phase2a_kernel()
{
    const unsigned int total  = g_ns1;
    const unsigned int stride = gridDim.x * blockDim.x;
    const int lane = threadIdx.x & 31;
    const int wid  = threadIdx.x >> 5;

    unsigned int local = 0;

    for (unsigned int s = blockIdx.x * blockDim.x + threadIdx.x;
         __any_sync(0xFFFFFFFFu, s < total); s += stride) {
        const bool has = (s < total);
        const float4 st = has ? g_st1[s]
                              : make_float4(10.0f, 0.0f, 10.0f, 0.0f);
        const float cr = st.x, ci = st.y;
        float zr = st.z, zi = st.w;
        float cnt = (float)K1;
        bool esc = false;

        #pragma unroll 1
        for (int chunk = 0; chunk < (B2 - K1) / 8; ++chunk) {
            #pragma unroll
            for (int j = 0; j < 8; ++j) {
                float t   = fmaf(zi, -zi, cr);
                float zr2 = fmaf(zr,  zr, t);
                float zi2 = fmaf(zr + zr, zi, ci);
                float mag = fmaf(zr2, zr2, zi2 * zi2);
                esc |= (mag > 4.0f);
                if (!esc) cnt += 1.0f;
                zr = zr2; zi = zi2;
            }
            if (__all_sync(0xFFFFFFFFu, esc)) break;
        }

        if (has & esc) local += (unsigned int)fabsf(cnt - 29.0f);

        // ---- dual-end partitioned re-compaction ----
        const bool surv = has & !esc;                      // cnt == B2
        const float magf = fmaf(zr, zr, zi * zi);
        const bool likely_esc = surv && (magf > 2.0f);
        const bool likely_set = surv && !(magf > 2.0f);

        const unsigned int maskA = __ballot_sync(0xFFFFFFFFu, likely_esc);
        if (maskA) {
            unsigned int b;
            if (lane == 0) b = atomicAdd(&g_ns2_lo, (unsigned int)__popc(maskA));
            b = __shfl_sync(0xFFFFFFFFu, b, 0);
            if (likely_esc) {
                unsigned int pos = b
                    + (unsigned int)__popc(maskA & ((1u << lane) - 1u));
                g_st2[pos] = make_float4(cr, ci, zr, zi);
            }
        }
        const unsigned int maskB = __ballot_sync(0xFFFFFFFFu, likely_set);
        if (maskB) {
            unsigned int b;
            if (lane == 0) b = atomicAdd(&g_ns2_hi, (unsigned int)__popc(maskB));
            b = __shfl_sync(0xFFFFFFFFu, b, 0);
            if (likely_set) {
                unsigned int pos = (unsigned int)NMAX - 1u
                    - (b + (unsigned int)__popc(maskB & ((1u << lane) - 1u)));
                g_st2[pos] = make_float4(cr, ci, zr, zi);
            }
        }
    }

    #pragma unroll
    for (int off = 16; off > 0; off >>= 1)
        local += __shfl_down_sync(0xFFFFFFFFu, local, off);

    __shared__ unsigned int warp_sums[P2_THREADS / 32];
    if (lane == 0) warp_sums[wid] = local;
    __syncthreads();

    if (wid == 0) {
        unsigned int v = (lane < P2_THREADS / 32) ? warp_sums[lane] : 0u;
        #pragma unroll
        for (int off = 4; off > 0; off >>= 1)
            v += __shfl_down_sync(0xFFFFFFFFu, v, off);
        if (lane == 0 && v)
            atomicAdd(&g_sum, (unsigned long long)v);
    }
}

// ---------------------------------------------------------------- phase 2b
// continue iters B2+1.. (64, overrun-clamped exactly); fused finalize
__global__ void __launch_bounds__(P2_THREADS) phase2b_kernel(
    float* __restrict__ out, int n)
{
    const unsigned int lo = g_ns2_lo;
    const unsigned int hi = g_ns2_hi;
    const unsigned int total  = lo + hi;
    const unsigned int stride = gridDim.x * blockDim.x;
    const int lane = threadIdx.x & 31;
    const int wid  = threadIdx.x >> 5;

    unsigned int local = 0;

    for (unsigned int s = blockIdx.x * blockDim.x + threadIdx.x;
         __any_sync(0xFFFFFFFFu, s < total); s += stride) {
        const bool has = (s < total);
        const unsigned int j = (s < lo) ? s
                             : (unsigned int)NMAX - 1u - (s - lo);
        const float4 st = has ? g_st2[j]
                              : make_float4(10.0f, 0.0f, 10.0f, 0.0f);
        const float cr = st.x, ci = st.y;
        float zr = st.z, zi = st.w;
        float cnt = (float)B2;
        bool esc = false;

        #pragma unroll 1
        for (int chunk = 0; chunk < 8; ++chunk) {
            #pragma unroll
            for (int jj = 0; jj < 8; ++jj) {
                float t   = fmaf(zi, -zi, cr);
                float zr2 = fmaf(zr,  zr, t);
                float zi2 = fmaf(zr + zr, zi, ci);
                float mag = fmaf(zr2, zr2, zi2 * zi2);
                esc |= (mag > 4.0f);
                if (!esc) cnt += 1.0f;
                zr = zr2; zi = zi2;
            }
            if (__all_sync(0xFFFFFFFFu, esc)) break;
        }

        if (has) {
            // escape at iter cnt+1 <= 100 -> |cnt-29|; else (cnt>99) -> 70,
            // exactly matching the reference cap at 100 iterations.
            unsigned int d = (esc && cnt <= 99.0f)
                           ? (unsigned int)fabsf(cnt - 29.0f) : 70u;
            local += d;
        }
    }

    #pragma unroll
    for (int off = 16; off > 0; off >>= 1)
        local += __shfl_down_sync(0xFFFFFFFFu, local, off);

    __shared__ unsigned int warp_sums[P2_THREADS / 32];
    if (lane == 0) warp_sums[wid] = local;
    __syncthreads();

    if (wid == 0) {
        unsigned int v = (lane < P2_THREADS / 32) ? warp_sums[lane] : 0u;
        #pragma unroll
        for (int off = 4; off > 0; off >>= 1)
            v += __shfl_down_sync(0xFFFFFFFFu, v, off);
        if (lane == 0 && v)
            atomicAdd(&g_sum, (unsigned long long)v);
    }

    // ---- last-block finalize ----
    if (threadIdx.x == 0) {
        __threadfence();
        unsigned int ticket = atomicAdd(&g_done, 1u);
        if (ticket == gridDim.x - 1u) {
            __threadfence();
            double sum = (double)g_sum;
            out[0] = (float)(sum * (0.1 / 30.0) / (double)n);
            g_sum = 0ULL;          // reset for next graph replay
            g_ns1 = 0u;
            g_ns2_lo = 0u;
            g_ns2_hi = 0u;
            g_done = 0u;
        }
    }
}

extern "C" void kernel_launch(void* const* d_in, const int* in_sizes, int n_in,
                              void* d_out, int out_size)
{
    const float* c_real = (const float*)d_in[0];
    const float* c_imag = (const float*)d_in[1];
    float* out = (float*)d_out;
    const int n = in_sizes[0];

    const int pts_per_block = P1_THREADS * P1_PTS;
    const int p1_blocks = (n + pts_per_block - 1) / pts_per_block;
    phase1_kernel<<<p1_blocks, P1_THREADS>>>(c_real, c_imag, n);

    phase2a_kernel<<<P2A_BLOCKS, P2_THREADS>>>();
    phase2b_kernel<<<P2B_BLOCKS, P2_THREADS>>>(out, n);
}